// round 9
// baseline (speedup 1.0000x reference)
#include <cuda_runtime.h>
#include <cstdint>

#define NA    100000
#define NEDGE 200000
#define HID   512
#define AD    133
#define BD    14
#define KIN   147   // AD + BD
#define KOUT  645   // AD + HID
#define KP1   160   // KIN padded to 32
#define KP2   512
#define KP3   672   // KOUT padded to 32
#define CK    32    // K chunk

// ---------------- scratch (static device globals; no allocation) ------------
__device__ float g_h0 [(size_t)NEDGE * HID];
__device__ float g_hA [(size_t)NEDGE * HID];
__device__ float g_hB [(size_t)NEDGE * HID];
__device__ float g_agg[(size_t)NA    * HID];
// pre-split weights (bf16 hi/lo), K-padded
__device__ __align__(16) unsigned short g_WiH[512 * KP1], g_WiL[512 * KP1];
__device__ __align__(16) unsigned short g_WhH[512 * KP2], g_WhL[512 * KP2];
__device__ __align__(16) unsigned short g_WoH[512 * KP3], g_WoL[512 * KP3];

// ---------------- helpers ----------------------------------------------------
__device__ __forceinline__ unsigned short f2bf(float x) {
    unsigned u = __float_as_uint(x);
    unsigned r = u + 0x7fffu + ((u >> 16) & 1u);   // RNE
    return (unsigned short)(r >> 16);
}
__device__ __forceinline__ float bf2f(unsigned short b) {
    return __uint_as_float(((unsigned)b) << 16);
}
__device__ __forceinline__ uint32_t smem_u32(const void* p) {
    uint32_t a;
    asm("{ .reg .u64 t; cvta.to.shared.u64 t, %1; cvt.u32.u64 %0, t; }" : "=r"(a) : "l"(p));
    return a;
}
__device__ __forceinline__ void ldsm4(uint32_t* r, uint32_t addr) {
    asm volatile("ldmatrix.sync.aligned.m8n8.x4.shared.b16 {%0,%1,%2,%3}, [%4];"
                 : "=r"(r[0]), "=r"(r[1]), "=r"(r[2]), "=r"(r[3]) : "r"(addr));
}
__device__ __forceinline__ void mma16816(float* d, const uint32_t* a,
                                         uint32_t b0, uint32_t b1) {
    asm volatile(
        "mma.sync.aligned.m16n8k16.row.col.f32.bf16.bf16.f32 "
        "{%0,%1,%2,%3}, {%4,%5,%6,%7}, {%8,%9}, {%0,%1,%2,%3};"
        : "+f"(d[0]), "+f"(d[1]), "+f"(d[2]), "+f"(d[3])
        : "r"(a[0]), "r"(a[1]), "r"(a[2]), "r"(a[3]), "r"(b0), "r"(b1));
}
__device__ __forceinline__ void cp16(uint32_t dst, const void* src) {
    asm volatile("cp.async.ca.shared.global [%0], [%1], 16;" :: "r"(dst), "l"(src));
}
// split 8 fp32 -> hi/lo bf16 packed (uint4 each = 8 bf16)
__device__ __forceinline__ void split8(const float* x, uint4& hi, uint4& lo) {
    unsigned hb[8], lb[8];
#pragma unroll
    for (int i = 0; i < 8; i++) {
        hb[i] = f2bf(x[i]);
        lb[i] = f2bf(x[i] - bf2f((unsigned short)hb[i]));
    }
    hi.x = hb[0] | (hb[1] << 16); hi.y = hb[2] | (hb[3] << 16);
    hi.z = hb[4] | (hb[5] << 16); hi.w = hb[6] | (hb[7] << 16);
    lo.x = lb[0] | (lb[1] << 16); lo.y = lb[2] | (lb[3] << 16);
    lo.z = lb[4] | (lb[5] << 16); lo.w = lb[6] | (lb[7] << 16);
}

// ---------------- utility kernels ------------------------------------------
__global__ void splitw_k(const float* __restrict__ W,
                         unsigned short* __restrict__ hi,
                         unsigned short* __restrict__ lo,
                         int N, int K, int Kp) {
    int idx = blockIdx.x * blockDim.x + threadIdx.x;
    if (idx >= N * Kp) return;
    int n = idx / Kp, k = idx - n * Kp;
    float v = (k < K) ? W[(size_t)n * K + k] : 0.f;
    unsigned short h = f2bf(v);
    hi[idx] = h;
    lo[idx] = f2bf(v - bf2f(h));
}

__global__ void zero_k(float4* __restrict__ p, int n4) {
    int i = blockIdx.x * blockDim.x + threadIdx.x;
    if (i < n4) p[i] = make_float4(0.f, 0.f, 0.f, 0.f);
}

__global__ void scatter_k(const float* __restrict__ h,
                          const int* __restrict__ dst,
                          const float* __restrict__ wgt,
                          float* __restrict__ agg) {
    int idx = blockIdx.x * blockDim.x + threadIdx.x;
    if (idx >= NEDGE * 128) return;
    int e = idx >> 7;
    int c = (idx & 127) << 2;
    int d = dst[e];
    float w = wgt ? wgt[e] : 1.0f;
    float4 hv = *(const float4*)(h + (size_t)e * HID + c);
    float* a = agg + (size_t)d * HID + c;
    atomicAdd(a + 0, w * hv.x);
    atomicAdd(a + 1, w * hv.y);
    atomicAdd(a + 2, w * hv.z);
    atomicAdd(a + 3, w * hv.w);
}

__global__ void batch_k(const int* __restrict__ b, float* __restrict__ out) {
    int i = blockIdx.x * blockDim.x + threadIdx.x;
    if (i < NA) out[i] = (float)b[i];
}

// ---------------- tensor-core (mma.sync) split-bf16 GEMM ---------------------
// C[M,512] = relu( A @ W^T (+ add) ).  CTA tile 128(M) x 128(N), K chunks of 32.
// 256 threads, 2 CTAs/SM. Warp grid 2(M) x 4(N); warp tile 64 x 32.
// MODE 1: A row e = [V[src[e]] ; E[e]]                          K=147
// MODE 2: A row e = agg[src[e]] - wgt[rev[e]] * Hin[rev[e]]     K=512, add=h0[row]
// MODE 3: A row i = [V[i] ; agg[i]]                             K=645, add=bias[col]
// smem per stage: A 16KB + B 16KB = 32KB; x2 = 64KB per CTA
#define SMEM_GEMM 65536

template <int MODE>
__global__ __launch_bounds__(256, 2)
void gemm_mma(const float* __restrict__ Hin,
              const unsigned short* __restrict__ WH,
              const unsigned short* __restrict__ WL,
              const float* __restrict__ Vf,
              const float* __restrict__ Eb,
              const int* __restrict__ src,
              const int* __restrict__ rev,
              const float* __restrict__ wgt,
              const float* __restrict__ agg,
              const float* __restrict__ h0,
              const float* __restrict__ bias,
              float* __restrict__ C,
              int M, int K, int Kp)
{
    extern __shared__ __align__(1024) char sm[];
    const uint32_t sb = smem_u32(sm);
    const int tid   = threadIdx.x;
    const int lane  = tid & 31;
    const int warp  = tid >> 5;         // 0..7
    const int warpM = warp >> 2;        // 0..1  (64 rows each)
    const int warpN = warp & 3;         // 0..3  (32 cols each)

    const int jb = blockIdx.x * 128;    // N block (fastest -> L2 reuse of A)
    const int mb = blockIdx.y * 128;    // M block

    // loader mapping: 2 threads per row, each covers 16 k-values (32B/plane)
    const int arow  = tid >> 1;         // 0..127
    const int aq    = tid & 1;          // 0..1
    const int agrow = mb + arow;
    const bool aok  = (agrow < M);

    int sidx = 0, ridx = 0; float wr = 0.f;
    if (MODE == 1) { if (aok) sidx = src[agrow]; }
    if (MODE == 2) { if (aok) { sidx = src[agrow]; ridx = rev[agrow]; wr = wgt[ridx]; } }

    float acc[4][4][4];
#pragma unroll
    for (int i = 0; i < 4; i++)
#pragma unroll
        for (int n = 0; n < 4; n++)
#pragma unroll
            for (int k = 0; k < 4; k++) acc[i][n][k] = 0.f;

    // A prefetch registers (16 fp32 per thread)
    float4 ag[4], hh[4];
    float  ar[16];

#define SW(o) ((o) ^ (((o) >> 3) & 0x70))

#define GLOAD_A(kb) do {                                                        \
    if (MODE == 2) {                                                            \
        if (aok) {                                                              \
            const float* ap = agg + (size_t)sidx * HID + (kb) + aq * 16;        \
            const float* hp = Hin + (size_t)ridx * HID + (kb) + aq * 16;        \
            _Pragma("unroll")                                                   \
            for (int u = 0; u < 4; u++) { ag[u] = ((const float4*)ap)[u];       \
                                          hh[u] = ((const float4*)hp)[u]; }     \
        }                                                                       \
    } else {                                                                    \
        _Pragma("unroll")                                                       \
        for (int i = 0; i < 16; i++) {                                          \
            int kk = (kb) + aq * 16 + i; float v = 0.f;                         \
            if (MODE == 1) {                                                    \
                if (aok && kk < KIN)                                            \
                    v = (kk < AD) ? Vf[(size_t)sidx * AD + kk]                  \
                                  : Eb[(size_t)agrow * BD + (kk - AD)];         \
            } else {                                                            \
                if (aok && kk < KOUT)                                           \
                    v = (kk < AD) ? Vf[(size_t)agrow * AD + kk]                 \
                                  : agg[(size_t)agrow * HID + (kk - AD)];       \
            }                                                                   \
            ar[i] = v;                                                          \
        }                                                                       \
    }                                                                           \
} while (0)

// B tile: pre-split bf16 hi/lo straight from global via cp.async.
// Row layout: 128B row = [hi 64B | lo 64B], SW128-swizzled. 2 threads/row.
#define CPB(kb, base) do {                                                      \
    const unsigned short* sH = WH + (size_t)(jb + arow) * Kp + (kb) + aq * 16;  \
    const unsigned short* sL = WL + (size_t)(jb + arow) * Kp + (kb) + aq * 16;  \
    int ob = arow * 128 + aq * 32;                                              \
    cp16(sb + (base) + 16384 + SW(ob),      sH);                                \
    cp16(sb + (base) + 16384 + SW(ob + 16), sH + 8);                            \
    cp16(sb + (base) + 16384 + SW(ob + 64), sL);                                \
    cp16(sb + (base) + 16384 + SW(ob + 80), sL + 8);                            \
    asm volatile("cp.async.commit_group;" ::: "memory");                        \
} while (0)

#define SSTORE_A(base) do {                                                     \
    float x[16];                                                                \
    if (MODE == 2) {                                                            \
        if (aok) {                                                              \
            _Pragma("unroll")                                                   \
            for (int u = 0; u < 4; u++) {                                       \
                x[u*4+0] = ag[u].x - wr * hh[u].x;                              \
                x[u*4+1] = ag[u].y - wr * hh[u].y;                              \
                x[u*4+2] = ag[u].z - wr * hh[u].z;                              \
                x[u*4+3] = ag[u].w - wr * hh[u].w;                              \
            }                                                                   \
        } else { _Pragma("unroll") for (int i = 0; i < 16; i++) x[i] = 0.f; }   \
    } else { _Pragma("unroll") for (int i = 0; i < 16; i++) x[i] = ar[i]; }     \
    uint4 h0v, l0v, h1v, l1v;                                                   \
    split8(x, h0v, l0v); split8(x + 8, h1v, l1v);                               \
    int oa = arow * 128 + aq * 32;                                              \
    *(uint4*)(sm + (base) + SW(oa))      = h0v;                                 \
    *(uint4*)(sm + (base) + SW(oa + 16)) = h1v;                                 \
    *(uint4*)(sm + (base) + SW(oa + 64)) = l0v;                                 \
    *(uint4*)(sm + (base) + SW(oa + 80)) = l1v;                                 \
} while (0)

#define DOMMA(base) do {                                                        \
    _Pragma("unroll")                                                           \
    for (int s = 0; s < 2; s++) {                                               \
        const int cb = s * 32 + ((lane >> 4) << 4);                             \
        uint32_t Bh[2][4], Bl[2][4];                                            \
        _Pragma("unroll")                                                       \
        for (int j = 0; j < 2; j++) {                                           \
            int r = warpN * 32 + j * 16 + (lane & 15);                          \
            int o = r * 128 + cb;                                               \
            ldsm4(Bh[j], sb + (base) + 16384 + SW(o));                          \
            int o2 = o + 64;                                                    \
            ldsm4(Bl[j], sb + (base) + 16384 + SW(o2));                         \
        }                                                                       \
        _Pragma("unroll")                                                       \
        for (int i = 0; i < 4; i++) {                                           \
            uint32_t Ah[4], Al[4];                                              \
            int r = warpM * 64 + i * 16 + (lane & 15);                          \
            int o = r * 128 + cb;                                               \
            ldsm4(Ah, sb + (base) + SW(o));                                     \
            int o2 = o + 64;                                                    \
            ldsm4(Al, sb + (base) + SW(o2));                                    \
            _Pragma("unroll")                                                   \
            for (int nt = 0; nt < 4; nt++) {                                    \
                int j = nt >> 1, sel = nt & 1;                                  \
                mma16816(acc[i][nt], Ah, Bh[j][sel], Bh[j][sel + 2]);           \
                mma16816(acc[i][nt], Al, Bh[j][sel], Bh[j][sel + 2]);           \
                mma16816(acc[i][nt], Ah, Bl[j][sel], Bl[j][sel + 2]);           \
            }                                                                   \
        }                                                                       \
    }                                                                           \
} while (0)

    const int nc = (K + CK - 1) / CK;
    // prologue: stage 0
    GLOAD_A(0);
    CPB(0, 0);
    SSTORE_A(0);
    asm volatile("cp.async.wait_group 0;" ::: "memory");
    __syncthreads();

    for (int t = 0; t < nc; t++) {
        const int base  = (t & 1) * 32768;
        const int obase = 32768 - base;
        const bool nxt = (t + 1 < nc);
        if (nxt) { GLOAD_A((t + 1) * CK); CPB((t + 1) * CK, obase); }
        DOMMA(base);
        if (nxt) {
            SSTORE_A(obase);
            asm volatile("cp.async.wait_group 0;" ::: "memory");
            __syncthreads();
        }
    }
#undef GLOAD_A
#undef CPB
#undef SSTORE_A
#undef DOMMA
#undef SW

    // ---- epilogue: acc -> (+h0/bias) -> relu -> C --------------------------
#pragma unroll
    for (int i = 0; i < 4; i++)
#pragma unroll
        for (int nt = 0; nt < 4; nt++) {
            const int r0 = mb + warpM * 64 + i * 16 + (lane >> 2);
            const int c  = jb + warpN * 32 + nt * 8 + (lane & 3) * 2;
#pragma unroll
            for (int hh2 = 0; hh2 < 2; hh2++) {
                const int r = r0 + hh2 * 8;
                if (r < M) {
                    float v0 = acc[i][nt][hh2 * 2 + 0];
                    float v1 = acc[i][nt][hh2 * 2 + 1];
                    const size_t base = (size_t)r * HID + c;
                    if (MODE == 2) {
                        float2 a = *(const float2*)(h0 + base);
                        v0 += a.x; v1 += a.y;
                    }
                    if (MODE == 3) { v0 += bias[c]; v1 += bias[c + 1]; }
                    float2 o;
                    o.x = fmaxf(v0, 0.f);
                    o.y = fmaxf(v1, 0.f);
                    *(float2*)(C + base) = o;
                }
            }
        }
}

// ---------------- driver -----------------------------------------------------
extern "C" void kernel_launch(void* const* d_in, const int* in_sizes, int n_in,
                              void* d_out, int out_size)
{
    const float* V     = (const float*)d_in[0];
    const float* E     = (const float*)d_in[1];
    const int*   eidx  = (const int*)d_in[2];
    const int*   rev   = (const int*)d_in[3];
    const int*   batch = (const int*)d_in[4];
    const float* wgt   = (const float*)d_in[5];
    const float* W_i   = (const float*)d_in[6];
    const float* W_h   = (const float*)d_in[7];
    const float* W_o   = (const float*)d_in[8];
    const float* b_o   = (const float*)d_in[9];

    const int* src = eidx;
    const int* dst = eidx + NEDGE;
    float* out = (float*)d_out;

    float *h0, *hA, *hB, *agg;
    cudaGetSymbolAddress((void**)&h0,  g_h0);
    cudaGetSymbolAddress((void**)&hA,  g_hA);
    cudaGetSymbolAddress((void**)&hB,  g_hB);
    cudaGetSymbolAddress((void**)&agg, g_agg);
    unsigned short *WiH, *WiL, *WhH, *WhL, *WoH, *WoL;
    cudaGetSymbolAddress((void**)&WiH, g_WiH);
    cudaGetSymbolAddress((void**)&WiL, g_WiL);
    cudaGetSymbolAddress((void**)&WhH, g_WhH);
    cudaGetSymbolAddress((void**)&WhL, g_WhL);
    cudaGetSymbolAddress((void**)&WoH, g_WoH);
    cudaGetSymbolAddress((void**)&WoL, g_WoL);

    cudaFuncSetAttribute(gemm_mma<1>, cudaFuncAttributeMaxDynamicSharedMemorySize, SMEM_GEMM);
    cudaFuncSetAttribute(gemm_mma<2>, cudaFuncAttributeMaxDynamicSharedMemorySize, SMEM_GEMM);
    cudaFuncSetAttribute(gemm_mma<3>, cudaFuncAttributeMaxDynamicSharedMemorySize, SMEM_GEMM);

    const dim3 blk(256);
    const dim3 grid_e(4, (NEDGE + 127) / 128);   // N-fastest for A reuse in L2
    const dim3 grid_a(4, (NA    + 127) / 128);
    const int  aggN4    = (NA * HID) / 4;
    const int  zeroGrid = (aggN4 + 255) / 256;
    const int  scatGrid = (NEDGE * 128 + 255) / 256;

    // h lives in d_out for the final step (skip the copy pass)
    float* hOut = out + (size_t)NA * HID + NA;

    // 0) pre-split weights to bf16 hi/lo (K-padded)
    splitw_k<<<(512 * KP1 + 255) / 256, 256>>>(W_i, WiH, WiL, 512, KIN,  KP1);
    splitw_k<<<(512 * KP2 + 255) / 256, 256>>>(W_h, WhH, WhL, 512, HID,  KP2);
    splitw_k<<<(512 * KP3 + 255) / 256, 256>>>(W_o, WoH, WoL, 512, KOUT, KP3);

    // 1) h0 = relu([V[src];E] @ W_i^T)
    gemm_mma<1><<<grid_e, blk, SMEM_GEMM>>>(nullptr, WiH, WiL, V, E, src, nullptr,
                                            nullptr, nullptr, nullptr, nullptr,
                                            h0, NEDGE, KIN, KP1);

    // 2) three message-passing steps; last one writes h directly into d_out
    const float* hin = h0;
    float* houts[3] = { hA, hB, hOut };
    for (int t = 0; t < 3; t++) {
        zero_k<<<zeroGrid, 256>>>((float4*)agg, aggN4);
        scatter_k<<<scatGrid, 256>>>(hin, dst, wgt, agg);
        gemm_mma<2><<<grid_e, blk, SMEM_GEMM>>>(hin, WhH, WhL, nullptr, nullptr,
                                                src, rev, wgt, agg, h0, nullptr,
                                                houts[t], NEDGE, HID, KP2);
        hin = houts[t];
    }
    float* hFinal = hOut;

    // 3) final aggregation (unweighted)
    zero_k<<<zeroGrid, 256>>>((float4*)agg, aggN4);
    scatter_k<<<scatGrid, 256>>>(hFinal, dst, nullptr, agg);

    // 4) h_atom = relu([V;agg] @ W_o^T + b_o) -> d_out[0 : 51.2M)
    gemm_mma<3><<<grid_a, blk, SMEM_GEMM>>>(nullptr, WoH, WoL, V, nullptr,
                                            nullptr, nullptr, nullptr, agg,
                                            nullptr, b_o, out, NA, KOUT, KP3);

    // 5) atom_batch as float -> d_out[51.2M : 51.3M)
    batch_k<<<(NA + 255) / 256, 256>>>(batch, out + (size_t)NA * HID);
}

// round 10
// speedup vs baseline: 1.1175x; 1.1175x over previous
#include <cuda_runtime.h>
#include <cstdint>

#define NA    100000
#define NEDGE 200000
#define HID   512
#define AD    133
#define BD    14
#define KIN   147   // AD + BD
#define KOUT  645   // AD + HID
#define KP1   160   // KIN padded to 32
#define KP2   512
#define KP3   672   // KOUT padded to 32
#define CK    32    // K chunk

// ---------------- scratch (static device globals; no allocation) ------------
__device__ float g_h0 [(size_t)NEDGE * HID];
__device__ float g_hA [(size_t)NEDGE * HID];
__device__ float g_hB [(size_t)NEDGE * HID];
__device__ float g_agg[(size_t)NA    * HID];
// dense pre-split message operand (bf16 hi/lo planes)
__device__ __align__(16) unsigned short g_mH[(size_t)NEDGE * HID];
__device__ __align__(16) unsigned short g_mL[(size_t)NEDGE * HID];
// pre-split weights (bf16 hi/lo), K-padded
__device__ __align__(16) unsigned short g_WiH[512 * KP1], g_WiL[512 * KP1];
__device__ __align__(16) unsigned short g_WhH[512 * KP2], g_WhL[512 * KP2];
__device__ __align__(16) unsigned short g_WoH[512 * KP3], g_WoL[512 * KP3];

// ---------------- helpers ----------------------------------------------------
__device__ __forceinline__ unsigned short f2bf(float x) {
    unsigned u = __float_as_uint(x);
    unsigned r = u + 0x7fffu + ((u >> 16) & 1u);   // RNE
    return (unsigned short)(r >> 16);
}
__device__ __forceinline__ float bf2f(unsigned short b) {
    return __uint_as_float(((unsigned)b) << 16);
}
__device__ __forceinline__ uint32_t smem_u32(const void* p) {
    uint32_t a;
    asm("{ .reg .u64 t; cvta.to.shared.u64 t, %1; cvt.u32.u64 %0, t; }" : "=r"(a) : "l"(p));
    return a;
}
__device__ __forceinline__ void ldsm4(uint32_t* r, uint32_t addr) {
    asm volatile("ldmatrix.sync.aligned.m8n8.x4.shared.b16 {%0,%1,%2,%3}, [%4];"
                 : "=r"(r[0]), "=r"(r[1]), "=r"(r[2]), "=r"(r[3]) : "r"(addr));
}
__device__ __forceinline__ void mma16816(float* d, const uint32_t* a,
                                         uint32_t b0, uint32_t b1) {
    asm volatile(
        "mma.sync.aligned.m16n8k16.row.col.f32.bf16.bf16.f32 "
        "{%0,%1,%2,%3}, {%4,%5,%6,%7}, {%8,%9}, {%0,%1,%2,%3};"
        : "+f"(d[0]), "+f"(d[1]), "+f"(d[2]), "+f"(d[3])
        : "r"(a[0]), "r"(a[1]), "r"(a[2]), "r"(a[3]), "r"(b0), "r"(b1));
}
__device__ __forceinline__ void cp16(uint32_t dst, const void* src) {
    asm volatile("cp.async.ca.shared.global [%0], [%1], 16;" :: "r"(dst), "l"(src));
}
// split 8 fp32 -> hi/lo bf16 packed (uint4 each = 8 bf16)
__device__ __forceinline__ void split8(const float* x, uint4& hi, uint4& lo) {
    unsigned hb[8], lb[8];
#pragma unroll
    for (int i = 0; i < 8; i++) {
        hb[i] = f2bf(x[i]);
        lb[i] = f2bf(x[i] - bf2f((unsigned short)hb[i]));
    }
    hi.x = hb[0] | (hb[1] << 16); hi.y = hb[2] | (hb[3] << 16);
    hi.z = hb[4] | (hb[5] << 16); hi.w = hb[6] | (hb[7] << 16);
    lo.x = lb[0] | (lb[1] << 16); lo.y = lb[2] | (lb[3] << 16);
    lo.z = lb[4] | (lb[5] << 16); lo.w = lb[6] | (lb[7] << 16);
}

// ---------------- utility kernels ------------------------------------------
__global__ void splitw_k(const float* __restrict__ W,
                         unsigned short* __restrict__ hi,
                         unsigned short* __restrict__ lo,
                         int N, int K, int Kp) {
    int idx = blockIdx.x * blockDim.x + threadIdx.x;
    if (idx >= N * Kp) return;
    int n = idx / Kp, k = idx - n * Kp;
    float v = (k < K) ? W[(size_t)n * K + k] : 0.f;
    unsigned short h = f2bf(v);
    hi[idx] = h;
    lo[idx] = f2bf(v - bf2f(h));
}

__global__ void zero_k(float4* __restrict__ p, int n4) {
    int i = blockIdx.x * blockDim.x + threadIdx.x;
    if (i < n4) p[i] = make_float4(0.f, 0.f, 0.f, 0.f);
}

__global__ void scatter_k(const float* __restrict__ h,
                          const int* __restrict__ dst,
                          const float* __restrict__ wgt,
                          float* __restrict__ agg) {
    int idx = blockIdx.x * blockDim.x + threadIdx.x;
    if (idx >= NEDGE * 128) return;
    int e = idx >> 7;
    int c = (idx & 127) << 2;
    int d = dst[e];
    float w = wgt ? wgt[e] : 1.0f;
    float4 hv = *(const float4*)(h + (size_t)e * HID + c);
    float* a = agg + (size_t)d * HID + c;
    atomicAdd(a + 0, w * hv.x);
    atomicAdd(a + 1, w * hv.y);
    atomicAdd(a + 2, w * hv.z);
    atomicAdd(a + 3, w * hv.w);
}

// message formation: m_e = agg[src[e]] - wgt[rev[e]] * h[rev[e]], pre-split bf16
__global__ void msg_k(const float* __restrict__ h,
                      const int* __restrict__ src,
                      const int* __restrict__ rev,
                      const float* __restrict__ wgt,
                      const float* __restrict__ agg,
                      unsigned short* __restrict__ mH,
                      unsigned short* __restrict__ mL) {
    int idx = blockIdx.x * blockDim.x + threadIdx.x;   // NEDGE * 64 threads
    if (idx >= NEDGE * 64) return;
    int e = idx >> 6;
    int c = (idx & 63) << 3;
    int s = src[e];
    int r = rev[e];
    float w = wgt[r];
    const float* ap = agg + (size_t)s * HID + c;
    const float* hp = h   + (size_t)r * HID + c;
    float4 a0 = *(const float4*)ap;
    float4 a1 = *(const float4*)(ap + 4);
    float4 h0 = *(const float4*)hp;
    float4 h1 = *(const float4*)(hp + 4);
    float x[8] = { a0.x - w * h0.x, a0.y - w * h0.y, a0.z - w * h0.z, a0.w - w * h0.w,
                   a1.x - w * h1.x, a1.y - w * h1.y, a1.z - w * h1.z, a1.w - w * h1.w };
    uint4 hi, lo;
    split8(x, hi, lo);
    *(uint4*)(mH + (size_t)e * HID + c) = hi;
    *(uint4*)(mL + (size_t)e * HID + c) = lo;
}

__global__ void batch_k(const int* __restrict__ b, float* __restrict__ out) {
    int i = blockIdx.x * blockDim.x + threadIdx.x;
    if (i < NA) out[i] = (float)b[i];
}

// ---------------- tensor-core (mma.sync) split-bf16 GEMM ---------------------
// C[M,512] = relu( A @ W^T (+ add) ).  CTA tile 128(M) x 128(N), K chunks of 32.
// MODE 0: A = dense pre-split bf16 (AH/AL) via cp.async            K=512, add=h0[row]
// MODE 1: A row e = [V[src[e]] ; E[e]]  (fused gather)             K=147
// MODE 3: A row i = [V[i] ; agg[i]]     (fused concat)             K=645, add=bias[col]
// smem per buffer: A 128x128B (hi|lo halves per row) + B same = 32KB; x2 = 64KB
#define SMEM_GEMM 65536

template <int MODE>
__global__ __launch_bounds__(512, 1)
void gemm_mma(const unsigned short* __restrict__ AH,
              const unsigned short* __restrict__ AL,
              const unsigned short* __restrict__ WH,
              const unsigned short* __restrict__ WL,
              const float* __restrict__ Vf,
              const float* __restrict__ Eb,
              const int* __restrict__ src,
              const float* __restrict__ agg,
              const float* __restrict__ h0,
              const float* __restrict__ bias,
              float* __restrict__ C,
              int M, int K, int Kp)
{
    extern __shared__ __align__(1024) char sm[];
    const uint32_t sb = smem_u32(sm);
    const int tid   = threadIdx.x;
    const int lane  = tid & 31;
    const int warp  = tid >> 5;
    const int warpM = warp >> 2;        // 0..3  (32 rows each)
    const int warpN = warp & 3;         // 0..3  (32 cols each)

    const int jb = blockIdx.x * 128;    // N block (fastest -> L2 reuse of A)
    const int mb = blockIdx.y * 128;    // M block

    // loader mapping: 4 threads per row, each covers 8 k-values (16B unit)
    const int arow  = tid >> 2;         // 0..127
    const int aq    = tid & 3;
    const int agrow = mb + arow;
    const bool aok  = (agrow < M);
    const int arow_c = aok ? agrow : 0; // clamped row for cp.async (no OOB)

    int sidx = 0;
    if (MODE == 1) { if (aok) sidx = src[agrow]; }

    float acc[2][4][4];
#pragma unroll
    for (int i = 0; i < 2; i++)
#pragma unroll
        for (int n = 0; n < 4; n++)
#pragma unroll
            for (int k = 0; k < 4; k++) acc[i][n][k] = 0.f;

    // A prefetch registers (gather modes only)
    float ar[8];

#define SW(o) ((o) ^ (((o) >> 3) & 0x70))

#define GLOAD_A(kb) do {                                                        \
    if (MODE != 0) {                                                            \
        _Pragma("unroll")                                                       \
        for (int i = 0; i < 8; i++) {                                           \
            int kk = (kb) + aq * 8 + i; float v = 0.f;                          \
            if (MODE == 1) {                                                    \
                if (aok && kk < KIN)                                            \
                    v = (kk < AD) ? Vf[(size_t)sidx * AD + kk]                  \
                                  : Eb[(size_t)agrow * BD + (kk - AD)];         \
            } else {                                                            \
                if (aok && kk < KOUT)                                           \
                    v = (kk < AD) ? Vf[(size_t)agrow * AD + kk]                 \
                                  : agg[(size_t)agrow * HID + (kk - AD)];       \
            }                                                                   \
            ar[i] = v;                                                          \
        }                                                                       \
    }                                                                           \
} while (0)

// A tile via cp.async (MODE 0) + B tile via cp.async (all modes); one commit.
#define CPTILE(kb, base) do {                                                   \
    if (MODE == 0) {                                                            \
        const unsigned short* aH = AH + (size_t)arow_c * Kp + (kb) + aq * 8;    \
        const unsigned short* aL = AL + (size_t)arow_c * Kp + (kb) + aq * 8;    \
        int oa = arow * 128 + aq * 16;                                          \
        cp16(sb + (base) + SW(oa),      aH);                                    \
        cp16(sb + (base) + SW(oa + 64), aL);                                    \
    }                                                                           \
    const unsigned short* sH = WH + (size_t)(jb + arow) * Kp + (kb) + aq * 8;   \
    const unsigned short* sL = WL + (size_t)(jb + arow) * Kp + (kb) + aq * 8;   \
    int ob = arow * 128 + aq * 16;                                              \
    cp16(sb + (base) + 16384 + SW(ob),      sH);                                \
    cp16(sb + (base) + 16384 + SW(ob + 64), sL);                                \
    asm volatile("cp.async.commit_group;" ::: "memory");                        \
} while (0)

#define SSTORE_A(base) do {                                                     \
    if (MODE != 0) {                                                            \
        float x[8];                                                             \
        _Pragma("unroll") for (int i = 0; i < 8; i++) x[i] = ar[i];             \
        uint4 hi, lo; split8(x, hi, lo);                                        \
        int oa = arow * 128 + aq * 16;                                          \
        *(uint4*)(sm + (base) + SW(oa))      = hi;                              \
        *(uint4*)(sm + (base) + SW(oa + 64)) = lo;                              \
    }                                                                           \
} while (0)

#define DOMMA(base) do {                                                        \
    _Pragma("unroll")                                                           \
    for (int s = 0; s < 2; s++) {                                               \
        uint32_t Ah[2][4], Al[2][4], Bh[2][4], Bl[2][4];                        \
        const int cb = s * 32 + ((lane >> 4) << 4);                             \
        _Pragma("unroll")                                                       \
        for (int i = 0; i < 2; i++) {                                           \
            int r = warpM * 32 + i * 16 + (lane & 15);                          \
            int o = r * 128 + cb;                                               \
            ldsm4(Ah[i], sb + (base) + SW(o));                                  \
            int o2 = o + 64;                                                    \
            ldsm4(Al[i], sb + (base) + SW(o2));                                 \
        }                                                                       \
        _Pragma("unroll")                                                       \
        for (int j = 0; j < 2; j++) {                                           \
            int r = warpN * 32 + j * 16 + (lane & 15);                          \
            int o = r * 128 + cb;                                               \
            ldsm4(Bh[j], sb + (base) + 16384 + SW(o));                          \
            int o2 = o + 64;                                                    \
            ldsm4(Bl[j], sb + (base) + 16384 + SW(o2));                         \
        }                                                                       \
        _Pragma("unroll")                                                       \
        for (int i = 0; i < 2; i++)                                             \
            _Pragma("unroll")                                                   \
            for (int nt = 0; nt < 4; nt++) {                                    \
                int j = nt >> 1, sel = nt & 1;                                  \
                mma16816(acc[i][nt], Ah[i], Bh[j][sel], Bh[j][sel + 2]);        \
                mma16816(acc[i][nt], Al[i], Bh[j][sel], Bh[j][sel + 2]);        \
                mma16816(acc[i][nt], Ah[i], Bl[j][sel], Bl[j][sel + 2]);        \
            }                                                                   \
    }                                                                           \
} while (0)

    const int nc = (K + CK - 1) / CK;
    // prologue: stage 0
    GLOAD_A(0);
    CPTILE(0, 0);
    SSTORE_A(0);
    asm volatile("cp.async.wait_group 0;" ::: "memory");
    __syncthreads();

    for (int t = 0; t < nc; t++) {
        const int base  = (t & 1) * 32768;
        const int obase = 32768 - base;
        const bool nxt = (t + 1 < nc);
        if (nxt) { GLOAD_A((t + 1) * CK); CPTILE((t + 1) * CK, obase); }
        DOMMA(base);
        if (nxt) {
            SSTORE_A(obase);
            asm volatile("cp.async.wait_group 0;" ::: "memory");
            __syncthreads();
        }
    }
#undef GLOAD_A
#undef CPTILE
#undef SSTORE_A
#undef DOMMA
#undef SW

    // ---- epilogue: acc -> (+h0/bias) -> relu -> C --------------------------
#pragma unroll
    for (int i = 0; i < 2; i++)
#pragma unroll
        for (int nt = 0; nt < 4; nt++) {
            const int r0 = mb + warpM * 32 + i * 16 + (lane >> 2);
            const int c  = jb + warpN * 32 + nt * 8 + (lane & 3) * 2;
#pragma unroll
            for (int hh = 0; hh < 2; hh++) {
                const int r = r0 + hh * 8;
                if (r < M) {
                    float v0 = acc[i][nt][hh * 2 + 0];
                    float v1 = acc[i][nt][hh * 2 + 1];
                    const size_t base = (size_t)r * HID + c;
                    if (MODE == 0) {
                        float2 a = *(const float2*)(h0 + base);
                        v0 += a.x; v1 += a.y;
                    }
                    if (MODE == 3) { v0 += bias[c]; v1 += bias[c + 1]; }
                    float2 o;
                    o.x = fmaxf(v0, 0.f);
                    o.y = fmaxf(v1, 0.f);
                    *(float2*)(C + base) = o;
                }
            }
        }
}

// ---------------- driver -----------------------------------------------------
extern "C" void kernel_launch(void* const* d_in, const int* in_sizes, int n_in,
                              void* d_out, int out_size)
{
    const float* V     = (const float*)d_in[0];
    const float* E     = (const float*)d_in[1];
    const int*   eidx  = (const int*)d_in[2];
    const int*   rev   = (const int*)d_in[3];
    const int*   batch = (const int*)d_in[4];
    const float* wgt   = (const float*)d_in[5];
    const float* W_i   = (const float*)d_in[6];
    const float* W_h   = (const float*)d_in[7];
    const float* W_o   = (const float*)d_in[8];
    const float* b_o   = (const float*)d_in[9];

    const int* src = eidx;
    const int* dst = eidx + NEDGE;
    float* out = (float*)d_out;

    float *h0, *hA, *hB, *agg;
    cudaGetSymbolAddress((void**)&h0,  g_h0);
    cudaGetSymbolAddress((void**)&hA,  g_hA);
    cudaGetSymbolAddress((void**)&hB,  g_hB);
    cudaGetSymbolAddress((void**)&agg, g_agg);
    unsigned short *mH, *mL;
    cudaGetSymbolAddress((void**)&mH, g_mH);
    cudaGetSymbolAddress((void**)&mL, g_mL);
    unsigned short *WiH, *WiL, *WhH, *WhL, *WoH, *WoL;
    cudaGetSymbolAddress((void**)&WiH, g_WiH);
    cudaGetSymbolAddress((void**)&WiL, g_WiL);
    cudaGetSymbolAddress((void**)&WhH, g_WhH);
    cudaGetSymbolAddress((void**)&WhL, g_WhL);
    cudaGetSymbolAddress((void**)&WoH, g_WoH);
    cudaGetSymbolAddress((void**)&WoL, g_WoL);

    cudaFuncSetAttribute(gemm_mma<0>, cudaFuncAttributeMaxDynamicSharedMemorySize, SMEM_GEMM);
    cudaFuncSetAttribute(gemm_mma<1>, cudaFuncAttributeMaxDynamicSharedMemorySize, SMEM_GEMM);
    cudaFuncSetAttribute(gemm_mma<3>, cudaFuncAttributeMaxDynamicSharedMemorySize, SMEM_GEMM);

    const dim3 blk(512);
    const dim3 grid_e(4, (NEDGE + 127) / 128);   // N-fastest for A reuse in L2
    const dim3 grid_a(4, (NA    + 127) / 128);
    const int  aggN4    = (NA * HID) / 4;
    const int  zeroGrid = (aggN4 + 255) / 256;
    const int  scatGrid = (NEDGE * 128 + 255) / 256;
    const int  msgGrid  = (NEDGE * 64  + 255) / 256;

    // h lives in d_out for the final step (skip the copy pass)
    float* hOut = out + (size_t)NA * HID + NA;

    // 0) pre-split weights to bf16 hi/lo (K-padded)
    splitw_k<<<(512 * KP1 + 255) / 256, 256>>>(W_i, WiH, WiL, 512, KIN,  KP1);
    splitw_k<<<(512 * KP2 + 255) / 256, 256>>>(W_h, WhH, WhL, 512, HID,  KP2);
    splitw_k<<<(512 * KP3 + 255) / 256, 256>>>(W_o, WoH, WoL, 512, KOUT, KP3);

    // 1) h0 = relu([V[src];E] @ W_i^T)
    gemm_mma<1><<<grid_e, blk, SMEM_GEMM>>>(nullptr, nullptr, WiH, WiL, V, E, src,
                                            nullptr, nullptr, nullptr,
                                            h0, NEDGE, KIN, KP1);

    // 2) three message-passing steps; last one writes h directly into d_out
    const float* hin = h0;
    float* houts[3] = { hA, hB, hOut };
    for (int t = 0; t < 3; t++) {
        zero_k<<<zeroGrid, 256>>>((float4*)agg, aggN4);
        scatter_k<<<scatGrid, 256>>>(hin, dst, wgt, agg);
        msg_k<<<msgGrid, 256>>>(hin, src, rev, wgt, agg, mH, mL);
        gemm_mma<0><<<grid_e, blk, SMEM_GEMM>>>(mH, mL, WhH, WhL, nullptr, nullptr,
                                                nullptr, nullptr, h0, nullptr,
                                                houts[t], NEDGE, HID, KP2);
        hin = houts[t];
    }
    float* hFinal = hOut;

    // 3) final aggregation (unweighted)
    zero_k<<<zeroGrid, 256>>>((float4*)agg, aggN4);
    scatter_k<<<scatGrid, 256>>>(hFinal, dst, nullptr, agg);

    // 4) h_atom = relu([V;agg] @ W_o^T + b_o) -> d_out[0 : 51.2M)
    gemm_mma<3><<<grid_a, blk, SMEM_GEMM>>>(nullptr, nullptr, WoH, WoL, V, nullptr,
                                            nullptr, agg, nullptr, b_o,
                                            out, NA, KOUT, KP3);

    // 5) atom_batch as float -> d_out[51.2M : 51.3M)
    batch_k<<<(NA + 255) / 256, 256>>>(batch, out + (size_t)NA * HID);
}

// round 11
// speedup vs baseline: 1.2015x; 1.0751x over previous
#include <cuda_runtime.h>
#include <cstdint>

#define NA    100000
#define NEDGE 200000
#define HID   512
#define AD    133
#define BD    14
#define KIN   147   // AD + BD
#define KOUT  645   // AD + HID
#define KP1   160   // KIN padded to 32
#define KP2   512
#define KP3   672   // KOUT padded to 32
#define CK    32    // K chunk

// ---------------- scratch (static device globals; no allocation) ------------
__device__ float g_h0 [(size_t)NEDGE * HID];
__device__ float g_hA [(size_t)NEDGE * HID];
__device__ float g_hB [(size_t)NEDGE * HID];
__device__ float g_agg[(size_t)NA    * HID];
// dense pre-split message operand (bf16 hi/lo planes)
__device__ __align__(16) unsigned short g_mH[(size_t)NEDGE * HID];
__device__ __align__(16) unsigned short g_mL[(size_t)NEDGE * HID];
// pre-split weights (bf16 hi/lo), K-padded
__device__ __align__(16) unsigned short g_WiH[512 * KP1], g_WiL[512 * KP1];
__device__ __align__(16) unsigned short g_WhH[512 * KP2], g_WhL[512 * KP2];
__device__ __align__(16) unsigned short g_WoH[512 * KP3], g_WoL[512 * KP3];

// ---------------- helpers ----------------------------------------------------
__device__ __forceinline__ unsigned short f2bf(float x) {
    unsigned u = __float_as_uint(x);
    unsigned r = u + 0x7fffu + ((u >> 16) & 1u);   // RNE
    return (unsigned short)(r >> 16);
}
__device__ __forceinline__ float bf2f(unsigned short b) {
    return __uint_as_float(((unsigned)b) << 16);
}
__device__ __forceinline__ uint32_t smem_u32(const void* p) {
    uint32_t a;
    asm("{ .reg .u64 t; cvta.to.shared.u64 t, %1; cvt.u32.u64 %0, t; }" : "=r"(a) : "l"(p));
    return a;
}
__device__ __forceinline__ void ldsm4(uint32_t* r, uint32_t addr) {
    asm volatile("ldmatrix.sync.aligned.m8n8.x4.shared.b16 {%0,%1,%2,%3}, [%4];"
                 : "=r"(r[0]), "=r"(r[1]), "=r"(r[2]), "=r"(r[3]) : "r"(addr));
}
__device__ __forceinline__ void mma16816(float* d, const uint32_t* a,
                                         uint32_t b0, uint32_t b1) {
    asm volatile(
        "mma.sync.aligned.m16n8k16.row.col.f32.bf16.bf16.f32 "
        "{%0,%1,%2,%3}, {%4,%5,%6,%7}, {%8,%9}, {%0,%1,%2,%3};"
        : "+f"(d[0]), "+f"(d[1]), "+f"(d[2]), "+f"(d[3])
        : "r"(a[0]), "r"(a[1]), "r"(a[2]), "r"(a[3]), "r"(b0), "r"(b1));
}
__device__ __forceinline__ void cp16(uint32_t dst, const void* src) {
    asm volatile("cp.async.ca.shared.global [%0], [%1], 16;" :: "r"(dst), "l"(src));
}
// split 8 fp32 -> hi/lo bf16 packed (uint4 each = 8 bf16)
__device__ __forceinline__ void split8(const float* x, uint4& hi, uint4& lo) {
    unsigned hb[8], lb[8];
#pragma unroll
    for (int i = 0; i < 8; i++) {
        hb[i] = f2bf(x[i]);
        lb[i] = f2bf(x[i] - bf2f((unsigned short)hb[i]));
    }
    hi.x = hb[0] | (hb[1] << 16); hi.y = hb[2] | (hb[3] << 16);
    hi.z = hb[4] | (hb[5] << 16); hi.w = hb[6] | (hb[7] << 16);
    lo.x = lb[0] | (lb[1] << 16); lo.y = lb[2] | (lb[3] << 16);
    lo.z = lb[4] | (lb[5] << 16); lo.w = lb[6] | (lb[7] << 16);
}

// ---------------- utility kernels ------------------------------------------
__global__ void splitw_k(const float* __restrict__ W,
                         unsigned short* __restrict__ hi,
                         unsigned short* __restrict__ lo,
                         int N, int K, int Kp) {
    int idx = blockIdx.x * blockDim.x + threadIdx.x;
    if (idx >= N * Kp) return;
    int n = idx / Kp, k = idx - n * Kp;
    float v = (k < K) ? W[(size_t)n * K + k] : 0.f;
    unsigned short h = f2bf(v);
    hi[idx] = h;
    lo[idx] = f2bf(v - bf2f(h));
}

__global__ void zero_k(float4* __restrict__ p, int n4) {
    int i = blockIdx.x * blockDim.x + threadIdx.x;
    if (i < n4) p[i] = make_float4(0.f, 0.f, 0.f, 0.f);
}

__global__ void scatter_k(const float* __restrict__ h,
                          const int* __restrict__ dst,
                          const float* __restrict__ wgt,
                          float* __restrict__ agg) {
    int idx = blockIdx.x * blockDim.x + threadIdx.x;
    if (idx >= NEDGE * 128) return;
    int e = idx >> 7;
    int c = (idx & 127) << 2;
    int d = dst[e];
    float w = wgt ? wgt[e] : 1.0f;
    float4 hv = *(const float4*)(h + (size_t)e * HID + c);
    float* a = agg + (size_t)d * HID + c;
    atomicAdd(a + 0, w * hv.x);
    atomicAdd(a + 1, w * hv.y);
    atomicAdd(a + 2, w * hv.z);
    atomicAdd(a + 3, w * hv.w);
}

// message formation: m_e = agg[src[e]] - wgt[rev[e]] * h[rev[e]], pre-split bf16
__global__ void msg_k(const float* __restrict__ h,
                      const int* __restrict__ src,
                      const int* __restrict__ rev,
                      const float* __restrict__ wgt,
                      const float* __restrict__ agg,
                      unsigned short* __restrict__ mH,
                      unsigned short* __restrict__ mL) {
    int idx = blockIdx.x * blockDim.x + threadIdx.x;   // NEDGE * 64 threads
    if (idx >= NEDGE * 64) return;
    int e = idx >> 6;
    int c = (idx & 63) << 3;
    int s = src[e];
    int r = rev[e];
    float w = wgt[r];
    const float* ap = agg + (size_t)s * HID + c;
    const float* hp = h   + (size_t)r * HID + c;
    float4 a0 = *(const float4*)ap;
    float4 a1 = *(const float4*)(ap + 4);
    float4 h0 = *(const float4*)hp;
    float4 h1 = *(const float4*)(hp + 4);
    float x[8] = { a0.x - w * h0.x, a0.y - w * h0.y, a0.z - w * h0.z, a0.w - w * h0.w,
                   a1.x - w * h1.x, a1.y - w * h1.y, a1.z - w * h1.z, a1.w - w * h1.w };
    uint4 hi, lo;
    split8(x, hi, lo);
    *(uint4*)(mH + (size_t)e * HID + c) = hi;
    *(uint4*)(mL + (size_t)e * HID + c) = lo;
}

__global__ void batch_k(const int* __restrict__ b, float* __restrict__ out) {
    int i = blockIdx.x * blockDim.x + threadIdx.x;
    if (i < NA) out[i] = (float)b[i];
}

// ---------------- tensor-core (mma.sync) split-bf16 GEMM ---------------------
// C[M,512] = relu( A @ W^T (+ add) ).  CTA tile 128(M) x 128(N), K chunks of 32.
// 256 threads, 2 CTAs/SM. Warp grid 2(M) x 4(N); warp tile 64 x 32.
// MODE 0: A = dense pre-split bf16 (AH/AL) via cp.async            K=512, add=h0[row]
// MODE 1: A row e = [V[src[e]] ; E[e]]  (fused gather)             K=147
// MODE 3: A row i = [V[i] ; agg[i]]     (fused concat)             K=645, add=bias[col]
// smem per stage: A 16KB + B 16KB = 32KB; x2 = 64KB per CTA
#define SMEM_GEMM 65536

template <int MODE>
__global__ __launch_bounds__(256, 2)
void gemm_mma(const unsigned short* __restrict__ AH,
              const unsigned short* __restrict__ AL,
              const unsigned short* __restrict__ WH,
              const unsigned short* __restrict__ WL,
              const float* __restrict__ Vf,
              const float* __restrict__ Eb,
              const int* __restrict__ src,
              const float* __restrict__ agg,
              const float* __restrict__ h0,
              const float* __restrict__ bias,
              float* __restrict__ C,
              int M, int K, int Kp)
{
    extern __shared__ __align__(1024) char sm[];
    const uint32_t sb = smem_u32(sm);
    const int tid   = threadIdx.x;
    const int lane  = tid & 31;
    const int warp  = tid >> 5;         // 0..7
    const int warpM = warp >> 2;        // 0..1  (64 rows each)
    const int warpN = warp & 3;         // 0..3  (32 cols each)

    const int jb = blockIdx.x * 128;    // N block (fastest -> L2 reuse of A)
    const int mb = blockIdx.y * 128;    // M block

    // loader mapping: 2 threads per row, each covers 16 k-values (32B/plane)
    const int arow  = tid >> 1;         // 0..127
    const int aq    = tid & 1;          // 0..1
    const int agrow = mb + arow;
    const bool aok  = (agrow < M);
    const int arow_c = aok ? agrow : 0; // clamped row for cp.async (no OOB)

    int sidx = 0;
    if (MODE == 1) { if (aok) sidx = src[agrow]; }

    float acc[4][4][4];
#pragma unroll
    for (int i = 0; i < 4; i++)
#pragma unroll
        for (int n = 0; n < 4; n++)
#pragma unroll
            for (int k = 0; k < 4; k++) acc[i][n][k] = 0.f;

    // A prefetch registers (gather modes only)
    float ar[16];

#define SW(o) ((o) ^ (((o) >> 3) & 0x70))

#define GLOAD_A(kb) do {                                                        \
    if (MODE != 0) {                                                            \
        _Pragma("unroll")                                                       \
        for (int i = 0; i < 16; i++) {                                          \
            int kk = (kb) + aq * 16 + i; float v = 0.f;                         \
            if (MODE == 1) {                                                    \
                if (aok && kk < KIN)                                            \
                    v = (kk < AD) ? Vf[(size_t)sidx * AD + kk]                  \
                                  : Eb[(size_t)agrow * BD + (kk - AD)];         \
            } else {                                                            \
                if (aok && kk < KOUT)                                           \
                    v = (kk < AD) ? Vf[(size_t)agrow * AD + kk]                 \
                                  : agg[(size_t)agrow * HID + (kk - AD)];       \
            }                                                                   \
            ar[i] = v;                                                          \
        }                                                                       \
    }                                                                           \
} while (0)

// A tile via cp.async (MODE 0) + B tile via cp.async (all modes); one commit.
#define CPTILE(kb, base) do {                                                   \
    if (MODE == 0) {                                                            \
        const unsigned short* aH = AH + (size_t)arow_c * Kp + (kb) + aq * 16;   \
        const unsigned short* aL = AL + (size_t)arow_c * Kp + (kb) + aq * 16;   \
        int oa = arow * 128 + aq * 32;                                          \
        cp16(sb + (base) + SW(oa),      aH);                                    \
        cp16(sb + (base) + SW(oa + 16), aH + 8);                                \
        cp16(sb + (base) + SW(oa + 64), aL);                                    \
        cp16(sb + (base) + SW(oa + 80), aL + 8);                                \
    }                                                                           \
    const unsigned short* sH = WH + (size_t)(jb + arow) * Kp + (kb) + aq * 16;  \
    const unsigned short* sL = WL + (size_t)(jb + arow) * Kp + (kb) + aq * 16;  \
    int ob = arow * 128 + aq * 32;                                              \
    cp16(sb + (base) + 16384 + SW(ob),      sH);                                \
    cp16(sb + (base) + 16384 + SW(ob + 16), sH + 8);                            \
    cp16(sb + (base) + 16384 + SW(ob + 64), sL);                                \
    cp16(sb + (base) + 16384 + SW(ob + 80), sL + 8);                            \
    asm volatile("cp.async.commit_group;" ::: "memory");                        \
} while (0)

#define SSTORE_A(base) do {                                                     \
    if (MODE != 0) {                                                            \
        uint4 h0v, l0v, h1v, l1v;                                               \
        split8(ar, h0v, l0v); split8(ar + 8, h1v, l1v);                         \
        int oa = arow * 128 + aq * 32;                                          \
        *(uint4*)(sm + (base) + SW(oa))      = h0v;                             \
        *(uint4*)(sm + (base) + SW(oa + 16)) = h1v;                             \
        *(uint4*)(sm + (base) + SW(oa + 64)) = l0v;                             \
        *(uint4*)(sm + (base) + SW(oa + 80)) = l1v;                             \
    }                                                                           \
} while (0)

#define DOMMA(base) do {                                                        \
    _Pragma("unroll")                                                           \
    for (int s = 0; s < 2; s++) {                                               \
        const int cb = s * 32 + ((lane >> 4) << 4);                             \
        uint32_t Bh[2][4], Bl[2][4];                                            \
        _Pragma("unroll")                                                       \
        for (int j = 0; j < 2; j++) {                                           \
            int r = warpN * 32 + j * 16 + (lane & 15);                          \
            int o = r * 128 + cb;                                               \
            ldsm4(Bh[j], sb + (base) + 16384 + SW(o));                          \
            int o2 = o + 64;                                                    \
            ldsm4(Bl[j], sb + (base) + 16384 + SW(o2));                         \
        }                                                                       \
        _Pragma("unroll")                                                       \
        for (int i = 0; i < 4; i++) {                                           \
            uint32_t Ah[4], Al[4];                                              \
            int r = warpM * 64 + i * 16 + (lane & 15);                          \
            int o = r * 128 + cb;                                               \
            ldsm4(Ah, sb + (base) + SW(o));                                     \
            int o2 = o + 64;                                                    \
            ldsm4(Al, sb + (base) + SW(o2));                                    \
            _Pragma("unroll")                                                   \
            for (int nt = 0; nt < 4; nt++) {                                    \
                int j = nt >> 1, sel = nt & 1;                                  \
                mma16816(acc[i][nt], Ah, Bh[j][sel], Bh[j][sel + 2]);           \
                mma16816(acc[i][nt], Al, Bh[j][sel], Bh[j][sel + 2]);           \
                mma16816(acc[i][nt], Ah, Bl[j][sel], Bl[j][sel + 2]);           \
            }                                                                   \
        }                                                                       \
    }                                                                           \
} while (0)

    const int nc = (K + CK - 1) / CK;
    // prologue: stage 0
    GLOAD_A(0);
    CPTILE(0, 0);
    SSTORE_A(0);
    asm volatile("cp.async.wait_group 0;" ::: "memory");
    __syncthreads();

    for (int t = 0; t < nc; t++) {
        const int base  = (t & 1) * 32768;
        const int obase = 32768 - base;
        const bool nxt = (t + 1 < nc);
        if (nxt) { GLOAD_A((t + 1) * CK); CPTILE((t + 1) * CK, obase); }
        DOMMA(base);
        if (nxt) {
            SSTORE_A(obase);
            asm volatile("cp.async.wait_group 0;" ::: "memory");
            __syncthreads();
        }
    }
#undef GLOAD_A
#undef CPTILE
#undef SSTORE_A
#undef DOMMA
#undef SW

    // ---- epilogue: acc -> (+h0/bias) -> relu -> C --------------------------
#pragma unroll
    for (int i = 0; i < 4; i++)
#pragma unroll
        for (int nt = 0; nt < 4; nt++) {
            const int r0 = mb + warpM * 64 + i * 16 + (lane >> 2);
            const int c  = jb + warpN * 32 + nt * 8 + (lane & 3) * 2;
#pragma unroll
            for (int hh2 = 0; hh2 < 2; hh2++) {
                const int r = r0 + hh2 * 8;
                if (r < M) {
                    float v0 = acc[i][nt][hh2 * 2 + 0];
                    float v1 = acc[i][nt][hh2 * 2 + 1];
                    const size_t base = (size_t)r * HID + c;
                    if (MODE == 0) {
                        float2 a = *(const float2*)(h0 + base);
                        v0 += a.x; v1 += a.y;
                    }
                    if (MODE == 3) { v0 += bias[c]; v1 += bias[c + 1]; }
                    float2 o;
                    o.x = fmaxf(v0, 0.f);
                    o.y = fmaxf(v1, 0.f);
                    *(float2*)(C + base) = o;
                }
            }
        }
}

// ---------------- driver -----------------------------------------------------
extern "C" void kernel_launch(void* const* d_in, const int* in_sizes, int n_in,
                              void* d_out, int out_size)
{
    const float* V     = (const float*)d_in[0];
    const float* E     = (const float*)d_in[1];
    const int*   eidx  = (const int*)d_in[2];
    const int*   rev   = (const int*)d_in[3];
    const int*   batch = (const int*)d_in[4];
    const float* wgt   = (const float*)d_in[5];
    const float* W_i   = (const float*)d_in[6];
    const float* W_h   = (const float*)d_in[7];
    const float* W_o   = (const float*)d_in[8];
    const float* b_o   = (const float*)d_in[9];

    const int* src = eidx;
    const int* dst = eidx + NEDGE;
    float* out = (float*)d_out;

    float *h0, *hA, *hB, *agg;
    cudaGetSymbolAddress((void**)&h0,  g_h0);
    cudaGetSymbolAddress((void**)&hA,  g_hA);
    cudaGetSymbolAddress((void**)&hB,  g_hB);
    cudaGetSymbolAddress((void**)&agg, g_agg);
    unsigned short *mH, *mL;
    cudaGetSymbolAddress((void**)&mH, g_mH);
    cudaGetSymbolAddress((void**)&mL, g_mL);
    unsigned short *WiH, *WiL, *WhH, *WhL, *WoH, *WoL;
    cudaGetSymbolAddress((void**)&WiH, g_WiH);
    cudaGetSymbolAddress((void**)&WiL, g_WiL);
    cudaGetSymbolAddress((void**)&WhH, g_WhH);
    cudaGetSymbolAddress((void**)&WhL, g_WhL);
    cudaGetSymbolAddress((void**)&WoH, g_WoH);
    cudaGetSymbolAddress((void**)&WoL, g_WoL);

    cudaFuncSetAttribute(gemm_mma<0>, cudaFuncAttributeMaxDynamicSharedMemorySize, SMEM_GEMM);
    cudaFuncSetAttribute(gemm_mma<1>, cudaFuncAttributeMaxDynamicSharedMemorySize, SMEM_GEMM);
    cudaFuncSetAttribute(gemm_mma<3>, cudaFuncAttributeMaxDynamicSharedMemorySize, SMEM_GEMM);

    const dim3 blk(256);
    const dim3 grid_e(4, (NEDGE + 127) / 128);   // N-fastest for A reuse in L2
    const dim3 grid_a(4, (NA    + 127) / 128);
    const int  aggN4    = (NA * HID) / 4;
    const int  zeroGrid = (aggN4 + 255) / 256;
    const int  scatGrid = (NEDGE * 128 + 255) / 256;
    const int  msgGrid  = (NEDGE * 64  + 255) / 256;

    // h lives in d_out for the final step (skip the copy pass)
    float* hOut = out + (size_t)NA * HID + NA;

    // 0) pre-split weights to bf16 hi/lo (K-padded)
    splitw_k<<<(512 * KP1 + 255) / 256, 256>>>(W_i, WiH, WiL, 512, KIN,  KP1);
    splitw_k<<<(512 * KP2 + 255) / 256, 256>>>(W_h, WhH, WhL, 512, HID,  KP2);
    splitw_k<<<(512 * KP3 + 255) / 256, 256>>>(W_o, WoH, WoL, 512, KOUT, KP3);

    // 1) h0 = relu([V[src];E] @ W_i^T)
    gemm_mma<1><<<grid_e, blk, SMEM_GEMM>>>(nullptr, nullptr, WiH, WiL, V, E, src,
                                            nullptr, nullptr, nullptr,
                                            h0, NEDGE, KIN, KP1);

    // 2) three message-passing steps; last one writes h directly into d_out
    const float* hin = h0;
    float* houts[3] = { hA, hB, hOut };
    for (int t = 0; t < 3; t++) {
        zero_k<<<zeroGrid, 256>>>((float4*)agg, aggN4);
        scatter_k<<<scatGrid, 256>>>(hin, dst, wgt, agg);
        msg_k<<<msgGrid, 256>>>(hin, src, rev, wgt, agg, mH, mL);
        gemm_mma<0><<<grid_e, blk, SMEM_GEMM>>>(mH, mL, WhH, WhL, nullptr, nullptr,
                                                nullptr, nullptr, h0, nullptr,
                                                houts[t], NEDGE, HID, KP2);
        hin = houts[t];
    }
    float* hFinal = hOut;

    // 3) final aggregation (unweighted)
    zero_k<<<zeroGrid, 256>>>((float4*)agg, aggN4);
    scatter_k<<<scatGrid, 256>>>(hFinal, dst, nullptr, agg);

    // 4) h_atom = relu([V;agg] @ W_o^T + b_o) -> d_out[0 : 51.2M)
    gemm_mma<3><<<grid_a, blk, SMEM_GEMM>>>(nullptr, nullptr, WoH, WoL, V, nullptr,
                                            nullptr, agg, nullptr, b_o,
                                            out, NA, KOUT, KP3);

    // 5) atom_batch as float -> d_out[51.2M : 51.3M)
    batch_k<<<(NA + 255) / 256, 256>>>(batch, out + (size_t)NA * HID);
}

// round 12
// speedup vs baseline: 1.7035x; 1.4178x over previous
#include <cuda_runtime.h>
#include <cuda_fp16.h>
#include <cstdint>

#define NA    100000
#define NEDGE 200000
#define HID   512
#define AD    133
#define BD    14
#define KIN   147   // AD + BD
#define KOUT  645   // AD + HID
#define KP1   160   // KIN padded to 32
#define KP2   512
#define KP3   672   // KOUT padded to 32
#define CK    32    // K chunk

// ---------------- scratch (static device globals; no allocation) ------------
__device__ float g_h0 [(size_t)NEDGE * HID];
__device__ float g_hA [(size_t)NEDGE * HID];
__device__ float g_hB [(size_t)NEDGE * HID];
__device__ float g_agg[(size_t)NA    * HID];
// dense fp16 message operand
__device__ __align__(16) unsigned short g_mF[(size_t)NEDGE * HID];
// fp16 weights, K-padded
__device__ __align__(16) unsigned short g_WiF[512 * KP1];
__device__ __align__(16) unsigned short g_WhF[512 * KP2];
__device__ __align__(16) unsigned short g_WoF[512 * KP3];

// ---------------- helpers ----------------------------------------------------
__device__ __forceinline__ uint32_t smem_u32(const void* p) {
    uint32_t a;
    asm("{ .reg .u64 t; cvta.to.shared.u64 t, %1; cvt.u32.u64 %0, t; }" : "=r"(a) : "l"(p));
    return a;
}
__device__ __forceinline__ void ldsm4(uint32_t* r, uint32_t addr) {
    asm volatile("ldmatrix.sync.aligned.m8n8.x4.shared.b16 {%0,%1,%2,%3}, [%4];"
                 : "=r"(r[0]), "=r"(r[1]), "=r"(r[2]), "=r"(r[3]) : "r"(addr));
}
__device__ __forceinline__ void mma16816(float* d, const uint32_t* a,
                                         uint32_t b0, uint32_t b1) {
    asm volatile(
        "mma.sync.aligned.m16n8k16.row.col.f32.f16.f16.f32 "
        "{%0,%1,%2,%3}, {%4,%5,%6,%7}, {%8,%9}, {%0,%1,%2,%3};"
        : "+f"(d[0]), "+f"(d[1]), "+f"(d[2]), "+f"(d[3])
        : "r"(a[0]), "r"(a[1]), "r"(a[2]), "r"(a[3]), "r"(b0), "r"(b1));
}
__device__ __forceinline__ void cp16(uint32_t dst, const void* src) {
    asm volatile("cp.async.ca.shared.global [%0], [%1], 16;" :: "r"(dst), "l"(src));
}
// pack 8 fp32 -> 8 fp16 (RNE) in one uint4
__device__ __forceinline__ uint4 pack8h(const float* x) {
    uint4 r;
    __half2 p0 = __floats2half2_rn(x[0], x[1]);
    __half2 p1 = __floats2half2_rn(x[2], x[3]);
    __half2 p2 = __floats2half2_rn(x[4], x[5]);
    __half2 p3 = __floats2half2_rn(x[6], x[7]);
    r.x = *(uint32_t*)&p0; r.y = *(uint32_t*)&p1;
    r.z = *(uint32_t*)&p2; r.w = *(uint32_t*)&p3;
    return r;
}

// ---------------- utility kernels ------------------------------------------
__global__ void cvtw_k(const float* __restrict__ W,
                       unsigned short* __restrict__ out,
                       int N, int K, int Kp) {
    int idx = blockIdx.x * blockDim.x + threadIdx.x;
    if (idx >= N * Kp) return;
    int n = idx / Kp, k = idx - n * Kp;
    float v = (k < K) ? W[(size_t)n * K + k] : 0.f;
    __half h = __float2half_rn(v);
    out[idx] = *(unsigned short*)&h;
}

__global__ void zero_k(float4* __restrict__ p, int n4) {
    int i = blockIdx.x * blockDim.x + threadIdx.x;
    if (i < n4) p[i] = make_float4(0.f, 0.f, 0.f, 0.f);
}

__global__ void scatter_k(const float* __restrict__ h,
                          const int* __restrict__ dst,
                          const float* __restrict__ wgt,
                          float* __restrict__ agg) {
    int idx = blockIdx.x * blockDim.x + threadIdx.x;
    if (idx >= NEDGE * 128) return;
    int e = idx >> 7;
    int c = (idx & 127) << 2;
    int d = dst[e];
    float w = wgt ? wgt[e] : 1.0f;
    float4 hv = *(const float4*)(h + (size_t)e * HID + c);
    float* a = agg + (size_t)d * HID + c;
    atomicAdd(a + 0, w * hv.x);
    atomicAdd(a + 1, w * hv.y);
    atomicAdd(a + 2, w * hv.z);
    atomicAdd(a + 3, w * hv.w);
}

// message formation: m_e = agg[src[e]] - wgt[rev[e]] * h[rev[e]], fp16 out
__global__ void msg_k(const float* __restrict__ h,
                      const int* __restrict__ src,
                      const int* __restrict__ rev,
                      const float* __restrict__ wgt,
                      const float* __restrict__ agg,
                      unsigned short* __restrict__ mF) {
    int idx = blockIdx.x * blockDim.x + threadIdx.x;   // NEDGE * 64 threads
    if (idx >= NEDGE * 64) return;
    int e = idx >> 6;
    int c = (idx & 63) << 3;
    int s = src[e];
    int r = rev[e];
    float w = wgt[r];
    const float* ap = agg + (size_t)s * HID + c;
    const float* hp = h   + (size_t)r * HID + c;
    float4 a0 = *(const float4*)ap;
    float4 a1 = *(const float4*)(ap + 4);
    float4 h0 = *(const float4*)hp;
    float4 h1 = *(const float4*)(hp + 4);
    float x[8] = { a0.x - w * h0.x, a0.y - w * h0.y, a0.z - w * h0.z, a0.w - w * h0.w,
                   a1.x - w * h1.x, a1.y - w * h1.y, a1.z - w * h1.z, a1.w - w * h1.w };
    *(uint4*)(mF + (size_t)e * HID + c) = pack8h(x);
}

__global__ void batch_k(const int* __restrict__ b, float* __restrict__ out) {
    int i = blockIdx.x * blockDim.x + threadIdx.x;
    if (i < NA) out[i] = (float)b[i];
}

// ---------------- tensor-core (mma.sync) fp16 GEMM ---------------------------
// C[M,512] = relu( A @ W^T (+ add) ).  CTA tile 128(M) x 128(N), K chunks of 32.
// 256 threads, 2 CTAs/SM. Warp grid 2(M) x 4(N); warp tile 64 x 32.
// Single-term fp16 (fp32 accumulate): 1 MMA per k16 step.
// MODE 0: A = dense fp16 (AF) via cp.async                         K=512, add=h0[row]
// MODE 1: A row e = [V[src[e]] ; E[e]]  (fused gather)             K=147
// MODE 3: A row i = [V[i] ; agg[i]]     (fused concat)             K=645, add=bias[col]
// smem rows are 128B (SW128); only first 64B of each row used (k0..31).
// per stage: A 16KB + B 16KB = 32KB; x2 = 64KB per CTA
#define SMEM_GEMM 65536

template <int MODE>
__global__ __launch_bounds__(256, 2)
void gemm_mma(const unsigned short* __restrict__ AF,
              const unsigned short* __restrict__ WF,
              const float* __restrict__ Vf,
              const float* __restrict__ Eb,
              const int* __restrict__ src,
              const float* __restrict__ agg,
              const float* __restrict__ h0,
              const float* __restrict__ bias,
              float* __restrict__ C,
              int M, int K, int Kp)
{
    extern __shared__ __align__(1024) char sm[];
    const uint32_t sb = smem_u32(sm);
    const int tid   = threadIdx.x;
    const int lane  = tid & 31;
    const int warp  = tid >> 5;         // 0..7
    const int warpM = warp >> 2;        // 0..1  (64 rows each)
    const int warpN = warp & 3;         // 0..3  (32 cols each)

    const int jb = blockIdx.x * 128;    // N block (fastest -> L2 reuse of A)
    const int mb = blockIdx.y * 128;    // M block

    // loader mapping: 2 threads per row, each covers 16 k-values (32B)
    const int arow  = tid >> 1;         // 0..127
    const int aq    = tid & 1;          // 0..1
    const int agrow = mb + arow;
    const bool aok  = (agrow < M);
    const int arow_c = aok ? agrow : 0; // clamped row for cp.async (no OOB)

    int sidx = 0;
    if (MODE == 1) { if (aok) sidx = src[agrow]; }

    float acc[4][4][4];
#pragma unroll
    for (int i = 0; i < 4; i++)
#pragma unroll
        for (int n = 0; n < 4; n++)
#pragma unroll
            for (int k = 0; k < 4; k++) acc[i][n][k] = 0.f;

    // A prefetch registers (gather modes only)
    float ar[16];

#define SW(o) ((o) ^ (((o) >> 3) & 0x70))

#define GLOAD_A(kb) do {                                                        \
    if (MODE != 0) {                                                            \
        _Pragma("unroll")                                                       \
        for (int i = 0; i < 16; i++) {                                          \
            int kk = (kb) + aq * 16 + i; float v = 0.f;                         \
            if (MODE == 1) {                                                    \
                if (aok && kk < KIN)                                            \
                    v = (kk < AD) ? Vf[(size_t)sidx * AD + kk]                  \
                                  : Eb[(size_t)agrow * BD + (kk - AD)];         \
            } else {                                                            \
                if (aok && kk < KOUT)                                           \
                    v = (kk < AD) ? Vf[(size_t)agrow * AD + kk]                 \
                                  : agg[(size_t)agrow * HID + (kk - AD)];       \
            }                                                                   \
            ar[i] = v;                                                          \
        }                                                                       \
    }                                                                           \
} while (0)

// A tile via cp.async (MODE 0) + B tile via cp.async (all modes); one commit.
#define CPTILE(kb, base) do {                                                   \
    if (MODE == 0) {                                                            \
        const unsigned short* aF = AF + (size_t)arow_c * Kp + (kb) + aq * 16;   \
        int oa = arow * 128 + aq * 32;                                          \
        cp16(sb + (base) + SW(oa),      aF);                                    \
        cp16(sb + (base) + SW(oa + 16), aF + 8);                                \
    }                                                                           \
    const unsigned short* sF = WF + (size_t)(jb + arow) * Kp + (kb) + aq * 16;  \
    int ob = arow * 128 + aq * 32;                                              \
    cp16(sb + (base) + 16384 + SW(ob),      sF);                                \
    cp16(sb + (base) + 16384 + SW(ob + 16), sF + 8);                            \
    asm volatile("cp.async.commit_group;" ::: "memory");                        \
} while (0)

#define SSTORE_A(base) do {                                                     \
    if (MODE != 0) {                                                            \
        int oa = arow * 128 + aq * 32;                                          \
        *(uint4*)(sm + (base) + SW(oa))      = pack8h(ar);                      \
        *(uint4*)(sm + (base) + SW(oa + 16)) = pack8h(ar + 8);                  \
    }                                                                           \
} while (0)

#define DOMMA(base) do {                                                        \
    _Pragma("unroll")                                                           \
    for (int s = 0; s < 2; s++) {                                               \
        const int cb = s * 32 + ((lane >> 4) << 4);                             \
        uint32_t Bf[2][4];                                                      \
        _Pragma("unroll")                                                       \
        for (int j = 0; j < 2; j++) {                                           \
            int r = warpN * 32 + j * 16 + (lane & 15);                          \
            int o = r * 128 + cb;                                               \
            ldsm4(Bf[j], sb + (base) + 16384 + SW(o));                          \
        }                                                                       \
        _Pragma("unroll")                                                       \
        for (int i = 0; i < 4; i++) {                                           \
            uint32_t Af[4];                                                     \
            int r = warpM * 64 + i * 16 + (lane & 15);                          \
            int o = r * 128 + cb;                                               \
            ldsm4(Af, sb + (base) + SW(o));                                     \
            _Pragma("unroll")                                                   \
            for (int nt = 0; nt < 4; nt++) {                                    \
                int j = nt >> 1, sel = nt & 1;                                  \
                mma16816(acc[i][nt], Af, Bf[j][sel], Bf[j][sel + 2]);           \
            }                                                                   \
        }                                                                       \
    }                                                                           \
} while (0)

    const int nc = (K + CK - 1) / CK;
    // prologue: stage 0
    GLOAD_A(0);
    CPTILE(0, 0);
    SSTORE_A(0);
    asm volatile("cp.async.wait_group 0;" ::: "memory");
    __syncthreads();

    for (int t = 0; t < nc; t++) {
        const int base  = (t & 1) * 32768;
        const int obase = 32768 - base;
        const bool nxt = (t + 1 < nc);
        if (nxt) { GLOAD_A((t + 1) * CK); CPTILE((t + 1) * CK, obase); }
        DOMMA(base);
        if (nxt) {
            SSTORE_A(obase);
            asm volatile("cp.async.wait_group 0;" ::: "memory");
            __syncthreads();
        }
    }
#undef GLOAD_A
#undef CPTILE
#undef SSTORE_A
#undef DOMMA
#undef SW

    // ---- epilogue: acc -> (+h0/bias) -> relu -> C --------------------------
#pragma unroll
    for (int i = 0; i < 4; i++)
#pragma unroll
        for (int nt = 0; nt < 4; nt++) {
            const int r0 = mb + warpM * 64 + i * 16 + (lane >> 2);
            const int c  = jb + warpN * 32 + nt * 8 + (lane & 3) * 2;
#pragma unroll
            for (int hh2 = 0; hh2 < 2; hh2++) {
                const int r = r0 + hh2 * 8;
                if (r < M) {
                    float v0 = acc[i][nt][hh2 * 2 + 0];
                    float v1 = acc[i][nt][hh2 * 2 + 1];
                    const size_t base = (size_t)r * HID + c;
                    if (MODE == 0) {
                        float2 a = *(const float2*)(h0 + base);
                        v0 += a.x; v1 += a.y;
                    }
                    if (MODE == 3) { v0 += bias[c]; v1 += bias[c + 1]; }
                    float2 o;
                    o.x = fmaxf(v0, 0.f);
                    o.y = fmaxf(v1, 0.f);
                    *(float2*)(C + base) = o;
                }
            }
        }
}

// ---------------- driver -----------------------------------------------------
extern "C" void kernel_launch(void* const* d_in, const int* in_sizes, int n_in,
                              void* d_out, int out_size)
{
    const float* V     = (const float*)d_in[0];
    const float* E     = (const float*)d_in[1];
    const int*   eidx  = (const int*)d_in[2];
    const int*   rev   = (const int*)d_in[3];
    const int*   batch = (const int*)d_in[4];
    const float* wgt   = (const float*)d_in[5];
    const float* W_i   = (const float*)d_in[6];
    const float* W_h   = (const float*)d_in[7];
    const float* W_o   = (const float*)d_in[8];
    const float* b_o   = (const float*)d_in[9];

    const int* src = eidx;
    const int* dst = eidx + NEDGE;
    float* out = (float*)d_out;

    float *h0, *hA, *hB, *agg;
    cudaGetSymbolAddress((void**)&h0,  g_h0);
    cudaGetSymbolAddress((void**)&hA,  g_hA);
    cudaGetSymbolAddress((void**)&hB,  g_hB);
    cudaGetSymbolAddress((void**)&agg, g_agg);
    unsigned short *mF, *WiF, *WhF, *WoF;
    cudaGetSymbolAddress((void**)&mF,  g_mF);
    cudaGetSymbolAddress((void**)&WiF, g_WiF);
    cudaGetSymbolAddress((void**)&WhF, g_WhF);
    cudaGetSymbolAddress((void**)&WoF, g_WoF);

    cudaFuncSetAttribute(gemm_mma<0>, cudaFuncAttributeMaxDynamicSharedMemorySize, SMEM_GEMM);
    cudaFuncSetAttribute(gemm_mma<1>, cudaFuncAttributeMaxDynamicSharedMemorySize, SMEM_GEMM);
    cudaFuncSetAttribute(gemm_mma<3>, cudaFuncAttributeMaxDynamicSharedMemorySize, SMEM_GEMM);

    const dim3 blk(256);
    const dim3 grid_e(4, (NEDGE + 127) / 128);   // N-fastest for A reuse in L2
    const dim3 grid_a(4, (NA    + 127) / 128);
    const int  aggN4    = (NA * HID) / 4;
    const int  zeroGrid = (aggN4 + 255) / 256;
    const int  scatGrid = (NEDGE * 128 + 255) / 256;
    const int  msgGrid  = (NEDGE * 64  + 255) / 256;

    // h lives in d_out for the final step (skip the copy pass)
    float* hOut = out + (size_t)NA * HID + NA;

    // 0) convert weights to fp16 (K-padded)
    cvtw_k<<<(512 * KP1 + 255) / 256, 256>>>(W_i, WiF, 512, KIN,  KP1);
    cvtw_k<<<(512 * KP2 + 255) / 256, 256>>>(W_h, WhF, 512, HID,  KP2);
    cvtw_k<<<(512 * KP3 + 255) / 256, 256>>>(W_o, WoF, 512, KOUT, KP3);

    // 1) h0 = relu([V[src];E] @ W_i^T)
    gemm_mma<1><<<grid_e, blk, SMEM_GEMM>>>(nullptr, WiF, V, E, src,
                                            nullptr, nullptr, nullptr,
                                            h0, NEDGE, KIN, KP1);

    // 2) three message-passing steps; last one writes h directly into d_out
    const float* hin = h0;
    float* houts[3] = { hA, hB, hOut };
    for (int t = 0; t < 3; t++) {
        zero_k<<<zeroGrid, 256>>>((float4*)agg, aggN4);
        scatter_k<<<scatGrid, 256>>>(hin, dst, wgt, agg);
        msg_k<<<msgGrid, 256>>>(hin, src, rev, wgt, agg, mF);
        gemm_mma<0><<<grid_e, blk, SMEM_GEMM>>>(mF, WhF, nullptr, nullptr, nullptr,
                                                nullptr, h0, nullptr,
                                                houts[t], NEDGE, HID, KP2);
        hin = houts[t];
    }
    float* hFinal = hOut;

    // 3) final aggregation (unweighted)
    zero_k<<<zeroGrid, 256>>>((float4*)agg, aggN4);
    scatter_k<<<scatGrid, 256>>>(hFinal, dst, nullptr, agg);

    // 4) h_atom = relu([V;agg] @ W_o^T + b_o) -> d_out[0 : 51.2M)
    gemm_mma<3><<<grid_a, blk, SMEM_GEMM>>>(nullptr, WoF, V, nullptr, nullptr,
                                            agg, nullptr, b_o,
                                            out, NA, KOUT, KP3);

    // 5) atom_batch as float -> d_out[51.2M : 51.3M)
    batch_k<<<(NA + 255) / 256, 256>>>(batch, out + (size_t)NA * HID);
}